// round 14
// baseline (speedup 1.0000x reference)
#include <cuda_runtime.h>
#include <cuda_bf16.h>
#include <cstdint>
#include <cstdio>

// Shapes (confirmed): B=4, T=1024, S=32, D=512; output = real part, fp32.
#define BT    4096
#define DIM   512
#define DIM2  1024
#define SLOTS 32

__device__ float g_W2[DIM2 * DIM2];   // qW @ kW^T   [1024 x 1024]
__device__ float g_b2[DIM2];          // kW @ qb     [1024]
__device__ float g_Qk[BT * DIM2];
__device__ float g_wH[BT * DIM2];

__device__ __forceinline__ unsigned tf32cvt(float f)
{
    unsigned r;
    asm("cvt.rna.tf32.f32 %0, %1;" : "=r"(r) : "f"(f));
    return r;
}
__device__ __forceinline__ int swA(int row, int col) { return col ^ (((row >> 2) & 3) << 3); }
__device__ __forceinline__ int swB(int col)          { return col ^ (((col >> 5) & 3) << 1); }

// ---------------------------------------------------------------------------
// TF32 GEMM, double-buffered: CTA tile 128(m) x 128(n), 256 threads (8 warps
// 2x4), warp tile 64x32 (4m x 4n m16n8k8), K-tile 16, reg prefetch + 2-stage
// smem, swizzled conflict-free fragment loads.
// CONCAT: 1 = A is concat(A=cur_r, A2=cur_i) rows of 512+512; 0 = plain [M,K]
// BMODE:  0 = B row-major [K x Bstride]; 1 = B is [N x K] (use B^T)
// EPI: 0 = C = (acc + bias?) * (rowscale? basescale*rowscale[m] : 1)
//      1 = real epilogue: C[m*512+n] = cur_r[m*512+n] + 0.1*(acc + bias[n])
// ---------------------------------------------------------------------------
template<int CONCAT, int BMODE, int EPI>
__global__ __launch_bounds__(256)
void gemm_db(const float* __restrict__ A, const float* __restrict__ A2,
             const float* __restrict__ B, int Bstride,
             const float* __restrict__ bias,
             const float* __restrict__ rowscale, float basescale,
             const float* __restrict__ cur_r,
             float* __restrict__ C,
             int M, int N, int K)
{
    __shared__ unsigned As[2][16][136];
    __shared__ unsigned Bs[2][16][136];

    const int tid  = threadIdx.x;
    const int lane = tid & 31;
    const int wid  = tid >> 5;
    const int wm   = wid & 1;
    const int wn   = wid >> 1;
    const int grp  = lane >> 2;
    const int tig  = lane & 3;
    const int bm   = blockIdx.y * 128;
    const int bn0  = blockIdx.x * 128;

    float acc[4][4][4];
#pragma unroll
    for (int a = 0; a < 4; a++)
#pragma unroll
        for (int b = 0; b < 4; b++)
#pragma unroll
            for (int c = 0; c < 4; c++) acc[a][b][c] = 0.f;

    // A loader: m = tid/2 (0..127), k = (tid%2)*8 ; two float4
    const int am  = tid >> 1;
    const int akk = (tid & 1) * 8;
    // B loader mode0: k = tid/16 (0..15), n = (tid%16)*8 ; two float4
    const int bkk = tid >> 4;
    const int bnn = (tid & 15) * 8;
    // B loader mode1: n = tid/2 (0..127), k = (tid%2)*8 ; two float4
    const int b1n = tid >> 1;
    const int b1k = (tid & 1) * 8;

    float4 aReg0, aReg1, bReg0, bReg1;

    auto ldg = [&](int k0) {
        {
            const long long m = bm + am;
            const long long k = k0 + akk;
            if (CONCAT) {
                if (k < 512) {
                    aReg0 = *(const float4*)(A + m * 512 + k);
                    aReg1 = *(const float4*)(A + m * 512 + k + 4);
                } else {
                    aReg0 = *(const float4*)(A2 + m * 512 + (k - 512));
                    aReg1 = *(const float4*)(A2 + m * 512 + (k - 512) + 4);
                }
            } else {
                aReg0 = *(const float4*)(A + m * (long long)K + k);
                aReg1 = *(const float4*)(A + m * (long long)K + k + 4);
            }
        }
        if (BMODE == 0) {
            const long long k = k0 + bkk;
            const long long n = bn0 + bnn;
            bReg0 = *(const float4*)(B + k * (long long)Bstride + n);
            bReg1 = *(const float4*)(B + k * (long long)Bstride + n + 4);
        } else {
            const long long n = bn0 + b1n;
            const long long k = k0 + b1k;
            bReg0 = *(const float4*)(B + n * (long long)K + k);
            bReg1 = *(const float4*)(B + n * (long long)K + k + 4);
        }
    };

    auto sts = [&](int buf) {
        const float av[8] = {aReg0.x, aReg0.y, aReg0.z, aReg0.w,
                             aReg1.x, aReg1.y, aReg1.z, aReg1.w};
#pragma unroll
        for (int i = 0; i < 8; i++)
            As[buf][akk + i][swA(akk + i, am)] = tf32cvt(av[i]);
        const float bv[8] = {bReg0.x, bReg0.y, bReg0.z, bReg0.w,
                             bReg1.x, bReg1.y, bReg1.z, bReg1.w};
        if (BMODE == 0) {
#pragma unroll
            for (int i = 0; i < 8; i++)
                Bs[buf][bkk][swB(bnn + i)] = tf32cvt(bv[i]);
        } else {
#pragma unroll
            for (int i = 0; i < 8; i++)
                Bs[buf][b1k + i][swB(b1n)] = tf32cvt(bv[i]);
        }
    };

    const int nIter = K / 16;
    ldg(0);
    sts(0);
    if (nIter > 1) ldg(16);
    __syncthreads();

    for (int it = 0; it < nIter; it++) {
        const int buf = it & 1;
        if (it + 1 < nIter) sts(buf ^ 1);       // regs hold tile it+1
        if (it + 2 < nIter) ldg((it + 2) * 16); // prefetch tile it+2

#pragma unroll
        for (int k8 = 0; k8 < 16; k8 += 8) {
            unsigned af[4][4];
#pragma unroll
            for (int mt = 0; mt < 4; mt++) {
                const int r = wm * 64 + mt * 16 + grp;
                af[mt][0] = As[buf][k8 + tig    ][swA(k8 + tig,     r)];
                af[mt][1] = As[buf][k8 + tig    ][swA(k8 + tig,     r + 8)];
                af[mt][2] = As[buf][k8 + tig + 4][swA(k8 + tig + 4, r)];
                af[mt][3] = As[buf][k8 + tig + 4][swA(k8 + tig + 4, r + 8)];
            }
            unsigned bf[4][2];
#pragma unroll
            for (int nt = 0; nt < 4; nt++) {
                const int n = wn * 32 + nt * 8 + grp;
                bf[nt][0] = Bs[buf][k8 + tig    ][swB(n)];
                bf[nt][1] = Bs[buf][k8 + tig + 4][swB(n)];
            }
#pragma unroll
            for (int mt = 0; mt < 4; mt++)
#pragma unroll
                for (int nt = 0; nt < 4; nt++)
                    asm volatile(
                        "mma.sync.aligned.m16n8k8.row.col.f32.tf32.tf32.f32 "
                        "{%0,%1,%2,%3}, {%4,%5,%6,%7}, {%8,%9}, {%0,%1,%2,%3};"
                        : "+f"(acc[mt][nt][0]), "+f"(acc[mt][nt][1]),
                          "+f"(acc[mt][nt][2]), "+f"(acc[mt][nt][3])
                        : "r"(af[mt][0]), "r"(af[mt][1]),
                          "r"(af[mt][2]), "r"(af[mt][3]),
                          "r"(bf[nt][0]), "r"(bf[nt][1]));
        }
        __syncthreads();
    }

    // --- epilogue ---
#pragma unroll
    for (int mt = 0; mt < 4; mt++) {
#pragma unroll
        for (int half = 0; half < 2; half++) {
            const long long m = bm + wm * 64 + mt * 16 + grp + half * 8;
            float rs = 1.f;
            if (EPI == 0 && rowscale != nullptr)
                rs = basescale * __ldg(rowscale + m);
#pragma unroll
            for (int nt = 0; nt < 4; nt++) {
                const long long n = bn0 + wn * 32 + nt * 8 + 2 * tig;
                float v0 = acc[mt][nt][half * 2 + 0];
                float v1 = acc[mt][nt][half * 2 + 1];
                if (bias != nullptr) {
                    v0 += __ldg(bias + n);
                    v1 += __ldg(bias + n + 1);
                }
                if (EPI == 0) {
                    C[m * N + n]     = v0 * rs;
                    C[m * N + n + 1] = v1 * rs;
                } else {
                    const long long f = m * 512 + n;
                    C[f]     = __ldg(cur_r + f)     + 0.1f * v0;
                    C[f + 1] = __ldg(cur_r + f + 1) + 0.1f * v1;
                }
            }
        }
    }
}

// b2[n] = sum_k kW[n,k] * qb[k]   (one warp per n)
__global__ __launch_bounds__(256)
void bias2_k(const float* __restrict__ kW, const float* __restrict__ qb,
             float* __restrict__ b2)
{
    const int n    = blockIdx.x * 8 + (threadIdx.x >> 5);
    const int lane = threadIdx.x & 31;
    const float* row = kW + (long long)n * 512;
    float s = 0.f;
#pragma unroll
    for (int k = lane * 4; k < 512; k += 128) {
        const float4 v = *(const float4*)(row + k);
        const float4 q = *(const float4*)(qb + k);
        s += v.x * q.x + v.y * q.y + v.z * q.z + v.w * q.w;
    }
#pragma unroll
    for (int o = 16; o; o >>= 1) s += __shfl_xor_sync(0xffffffffu, s, o);
    if (lane == 0) b2[n] = s;
}

// ---------------------------------------------------------------------------
// Two-phase attention (R13 WIN, unchanged): 81% DRAM, near roofline.
// ---------------------------------------------------------------------------
__global__ __launch_bounds__(256)
void attn_2p(const float* __restrict__ hr, const float* __restrict__ hi)
{
    __shared__ __align__(16) float shQ[DIM2];
    __shared__ float shS[SLOTS];
    __shared__ float shW[SLOTS];

    const int bt  = blockIdx.x;
    const int tid = threadIdx.x;
    const int w   = tid >> 5;
    const int c   = tid & 31;

    *(float4*)&shQ[tid * 4] = *(const float4*)(g_Qk + (size_t)bt * DIM2 + tid * 4);
    __syncthreads();

    const float* baseR = hr + (size_t)bt * (SLOTS * 512);
    const float* baseI = hi + (size_t)bt * (SLOTS * 512);

#pragma unroll
    for (int si = 0; si < 4; si++) {
        const int s = w + si * 8;
        const float* prow = baseR + (size_t)s * 512 + 4 * c;
        const float* irow = baseI + (size_t)s * 512 + 4 * c;
        float p = 0.f;
#pragma unroll
        for (int k = 0; k < 4; k++) {
            const float4 h = *(const float4*)(prow + k * 128);
            const float4 q = *(const float4*)&shQ[k * 128 + 4 * c];
            p += h.x * q.x + h.y * q.y + h.z * q.z + h.w * q.w;
        }
#pragma unroll
        for (int k = 0; k < 4; k++) {
            const float4 h = *(const float4*)(irow + k * 128);
            const float4 q = *(const float4*)&shQ[512 + k * 128 + 4 * c];
            p += h.x * q.x + h.y * q.y + h.z * q.z + h.w * q.w;
        }
#pragma unroll
        for (int off = 16; off; off >>= 1)
            p += __shfl_xor_sync(0xffffffffu, p, off);
        if (c == 0) shS[s] = p;
    }
    __syncthreads();

    if (tid < SLOTS) {
        float m = -1e30f;
#pragma unroll
        for (int i = 0; i < SLOTS; i++) m = fmaxf(m, shS[i]);
        shW[tid] = __expf(shS[tid] - m);
    }
    __syncthreads();
    float L = 0.f;
#pragma unroll
    for (int i = 0; i < SLOTS; i++) L += shW[i];
    const float invL = 1.f / L;

    const int j = tid * 4;
    const float* src = (j < 512) ? (baseR + j) : (baseI + (j - 512));
    float4 acc = make_float4(0.f, 0.f, 0.f, 0.f);
#pragma unroll 8
    for (int s = 0; s < SLOTS; s++) {
        const float4 h = *(const float4*)(src + (size_t)s * 512);
        const float ws = shW[s];
        acc.x += ws * h.x;
        acc.y += ws * h.y;
        acc.z += ws * h.z;
        acc.w += ws * h.w;
    }
    acc.x *= invL; acc.y *= invL; acc.z *= invL; acc.w *= invL;
    *(float4*)&g_wH[(size_t)bt * DIM2 + j] = acc;
}

// ---------------------------------------------------------------------------
// Host-side staged diagnostics (only on the non-captured correctness call).
// ---------------------------------------------------------------------------
static bool kl_capturing()
{
    cudaStreamCaptureStatus st = cudaStreamCaptureStatusNone;
    cudaError_t e = cudaStreamIsCapturing((cudaStream_t)0, &st);
    if (e != cudaSuccess) { (void)cudaGetLastError(); return true; }
    return st != cudaStreamCaptureStatusNone;
}
static cudaError_t kl_poll()
{
    cudaEvent_t ev;
    if (cudaEventCreateWithFlags(&ev, cudaEventDisableTiming) != cudaSuccess)
        return cudaGetLastError();
    cudaEventRecord(ev, (cudaStream_t)0);
    cudaError_t e;
    do { e = cudaEventQuery(ev); } while (e == cudaErrorNotReady);
    cudaEventDestroy(ev);
    return e;
}
static void kl_stage(bool diag, const char* name, bool* dead)
{
    if (!diag || *dead) return;
    cudaError_t e = kl_poll();
    if (e != cudaSuccess) {
        fprintf(stderr, "[KLDIAG] stage %s -> %s\n", name, cudaGetErrorString(e));
        *dead = true;
    }
}

// ---------------------------------------------------------------------------
extern "C" void kernel_launch(void* const* d_in, const int* in_sizes, int n_in,
                              void* d_out, int out_size)
{
    const bool diag = !kl_capturing();
    if (n_in < 11) return;

    // Confirmed insertion order, all fp32:
    // 0=hist_real 1=hist_imag 2=cur_r 3=cur_i 4=conf 5=qW 6=qb 7=kW 8=kb 9=vW 10=vb
    const float* hr   = (const float*)d_in[0];
    const float* hi   = (const float*)d_in[1];
    const float* cr   = (const float*)d_in[2];
    const float* ci   = (const float*)d_in[3];
    const float* conf = (const float*)d_in[4];
    const float* qW   = (const float*)d_in[5];
    const float* qb   = (const float*)d_in[6];
    const float* kW   = (const float*)d_in[7];
    // d_in[8] = kb: softmax-invariant, unused
    const float* vW   = (const float*)d_in[9];
    const float* vb   = (const float*)d_in[10];
    float* out = (float*)d_out;   // out_size fp32 elements = real part

    float *pW2 = nullptr, *pB2 = nullptr, *pQk = nullptr, *pwH = nullptr;
    cudaGetSymbolAddress((void**)&pW2, g_W2);
    cudaGetSymbolAddress((void**)&pB2, g_b2);
    cudaGetSymbolAddress((void**)&pQk, g_Qk);
    cudaGetSymbolAddress((void**)&pwH, g_wH);
    if (!pW2 || !pB2 || !pQk || !pwH) return;

    const float scale = 0.044194173824159216f;   // 512^-0.5
    bool dead = false;

    // 1a) W2 = qW @ kW^T   [1024,1024], K=512
    gemm_db<0, 1, 0><<<dim3(DIM2 / 128, DIM2 / 128), 256>>>(
        qW, nullptr, kW, 0, nullptr, nullptr, 1.f, nullptr, pW2,
        DIM2, DIM2, DIM);
    // 1b) b2 = kW @ qb
    bias2_k<<<DIM2 / 8, 256>>>(kW, qb, pB2);
    kl_stage(diag, "w2", &dead);
    if (dead) return;

    // 2) Qk = (cur2 @ W2 + b2) * scale * conf[m]   [4096,1024], K=1024
    gemm_db<1, 0, 0><<<dim3(DIM2 / 128, BT / 128), 256>>>(
        cr, ci, pW2, DIM2, pB2, conf, scale, nullptr, pQk, BT, DIM2, DIM2);
    kl_stage(diag, "qk", &dead);
    if (dead) return;

    // 3) two-phase softmax attention -> g_wH
    attn_2p<<<BT, 256>>>(hr, hi);
    kl_stage(diag, "attn", &dead);
    if (dead) return;

    // 4) out = cur_r + 0.1 * (wH @ vW[:,0:512] + vb[0:512])   (real part)
    gemm_db<0, 0, 1><<<dim3(DIM / 128, BT / 128), 256>>>(
        pwH, nullptr, vW, DIM2, vb, nullptr, 1.f, cr, out, BT, DIM, DIM2);
    kl_stage(diag, "gemm4", &dead);
}

// round 15
// speedup vs baseline: 1.3055x; 1.3055x over previous
#include <cuda_runtime.h>
#include <cuda_bf16.h>
#include <cstdint>
#include <cstdio>

// Shapes (confirmed): B=4, T=1024, S=32, D=512; output = real part, fp32.
#define BT    4096
#define DIM   512
#define DIM2  1024
#define SLOTS 32

__device__ float g_W2[DIM2 * DIM2];   // qW @ kW^T   [1024 x 1024]
__device__ float g_b2[DIM2];          // kW @ qb     [1024]
__device__ float g_Qk[BT * DIM2];
__device__ float g_wH[BT * DIM2];

// Pack two fp32 -> bf16x2 word (lo = first/lower-k element).
__device__ __forceinline__ unsigned bf16pack(float lo, float hi)
{
    unsigned r;
    asm("cvt.rn.bf16x2.f32 %0, %1, %2;" : "=r"(r) : "f"(hi), "f"(lo));
    return r;
}
// Column swizzle: XOR 16 for word-rows >= 4 (conflict-free STS + fragment LDS).
__device__ __forceinline__ int swC(int kk2, int col)
{
    return col ^ (((kk2 >> 2) & 1) << 4);
}

// ---------------------------------------------------------------------------
// BF16 tensor-core GEMM (fp32 accum), double-buffered: CTA 128x128, 256 thr
// (8 warps 2x4), warp tile 64x32 (4m x 4n m16n8k16), K-tile 16 (=8 bf16x2
// word rows), reg prefetch + 2-stage smem, XOR16 swizzle.
// CONCAT: 1 = A is concat(A=cur_r, A2=cur_i) rows of 512+512; 0 = plain [M,K]
// BMODE:  0 = B row-major [K x Bstride]; 1 = B is [N x K] (use B^T)
// EPI: 0 = C = (acc + bias?) * (rowscale? basescale*rowscale[m] : 1)
//      1 = real epilogue: C[m*512+n] = cur_r[m*512+n] + 0.1*(acc + bias[n])
// ---------------------------------------------------------------------------
template<int CONCAT, int BMODE, int EPI>
__global__ __launch_bounds__(256, 2)
void gemm_bf(const float* __restrict__ A, const float* __restrict__ A2,
             const float* __restrict__ B, int Bstride,
             const float* __restrict__ bias,
             const float* __restrict__ rowscale, float basescale,
             const float* __restrict__ cur_r,
             float* __restrict__ C,
             int M, int N, int K)
{
    __shared__ unsigned As16[2][8][136];   // [k/2][m] bf16x2 packed along k
    __shared__ unsigned Bs16[2][8][136];   // [k/2][n]

    const int tid  = threadIdx.x;
    const int lane = tid & 31;
    const int wid  = tid >> 5;
    const int wm   = wid & 1;
    const int wn   = wid >> 1;
    const int grp  = lane >> 2;
    const int tig  = lane & 3;
    const int bm   = blockIdx.y * 128;
    const int bn0  = blockIdx.x * 128;

    float acc[4][4][4];
#pragma unroll
    for (int a = 0; a < 4; a++)
#pragma unroll
        for (int b = 0; b < 4; b++)
#pragma unroll
            for (int c = 0; c < 4; c++) acc[a][b][c] = 0.f;

    // A loader: m = tid/2 (0..127), k = (tid&1)*8 .. +8  -> word rows (tid&1)*4+i
    const int am   = tid >> 1;
    const int akk2 = (tid & 1) * 4;
    // B mode0 loader: word row kk = tid/32 (0..7) -> k rows 2kk,2kk+1; n = (tid%32)*4
    const int bkk  = tid >> 5;
    const int bnn  = (lane) * 4;
    // B mode1 loader: n = tid/2 (0..127), word rows (tid&1)*4+i
    const int b1n  = tid >> 1;

    float4 aReg0, aReg1, bReg0, bReg1;

    auto ldg = [&](int k0) {
        {
            const long long m = bm + am;
            const long long k = k0 + akk2 * 2;
            if (CONCAT) {
                if (k < 512) {
                    aReg0 = *(const float4*)(A + m * 512 + k);
                    aReg1 = *(const float4*)(A + m * 512 + k + 4);
                } else {
                    aReg0 = *(const float4*)(A2 + m * 512 + (k - 512));
                    aReg1 = *(const float4*)(A2 + m * 512 + (k - 512) + 4);
                }
            } else {
                aReg0 = *(const float4*)(A + m * (long long)K + k);
                aReg1 = *(const float4*)(A + m * (long long)K + k + 4);
            }
        }
        if (BMODE == 0) {
            const long long k = k0 + bkk * 2;
            const long long n = bn0 + bnn;
            bReg0 = *(const float4*)(B + k * (long long)Bstride + n);
            bReg1 = *(const float4*)(B + (k + 1) * (long long)Bstride + n);
        } else {
            const long long n = bn0 + b1n;
            const long long k = k0 + akk2 * 2;   // same parity mapping as A
            bReg0 = *(const float4*)(B + n * (long long)K + k);
            bReg1 = *(const float4*)(B + n * (long long)K + k + 4);
        }
    };

    auto sts = [&](int buf) {
        {   // A: pack k-pairs from 8 consecutive k floats
            const float av[8] = {aReg0.x, aReg0.y, aReg0.z, aReg0.w,
                                 aReg1.x, aReg1.y, aReg1.z, aReg1.w};
#pragma unroll
            for (int i = 0; i < 4; i++)
                As16[buf][akk2 + i][swC(akk2 + i, am)] =
                    bf16pack(av[2 * i], av[2 * i + 1]);
        }
        if (BMODE == 0) {
            // pack across the two k-rows: word(n+i) = (h(k,n+i), h(k+1,n+i))
            const int col = swC(bkk, bnn);
            Bs16[buf][bkk][col + 0] = bf16pack(bReg0.x, bReg1.x);
            Bs16[buf][bkk][col + 1] = bf16pack(bReg0.y, bReg1.y);
            Bs16[buf][bkk][col + 2] = bf16pack(bReg0.z, bReg1.z);
            Bs16[buf][bkk][col + 3] = bf16pack(bReg0.w, bReg1.w);
        } else {
            const float bv[8] = {bReg0.x, bReg0.y, bReg0.z, bReg0.w,
                                 bReg1.x, bReg1.y, bReg1.z, bReg1.w};
#pragma unroll
            for (int i = 0; i < 4; i++)
                Bs16[buf][akk2 + i][swC(akk2 + i, b1n)] =
                    bf16pack(bv[2 * i], bv[2 * i + 1]);
        }
    };

    const int nIter = K / 16;
    ldg(0);
    sts(0);
    if (nIter > 1) ldg(16);
    __syncthreads();

    for (int it = 0; it < nIter; it++) {
        const int buf = it & 1;
        if (it + 1 < nIter) sts(buf ^ 1);       // regs hold tile it+1
        if (it + 2 < nIter) ldg((it + 2) * 16); // prefetch tile it+2

        unsigned bf[4][2];
#pragma unroll
        for (int nt = 0; nt < 4; nt++) {
            const int n = wn * 32 + nt * 8 + grp;
            bf[nt][0] = Bs16[buf][tig    ][swC(tig,     n)];
            bf[nt][1] = Bs16[buf][tig + 4][swC(tig + 4, n)];
        }
#pragma unroll
        for (int mt = 0; mt < 4; mt++) {
            const int r = wm * 64 + mt * 16 + grp;
            unsigned a0 = As16[buf][tig    ][swC(tig,     r)];
            unsigned a1 = As16[buf][tig    ][swC(tig,     r + 8)];
            unsigned a2 = As16[buf][tig + 4][swC(tig + 4, r)];
            unsigned a3 = As16[buf][tig + 4][swC(tig + 4, r + 8)];
#pragma unroll
            for (int nt = 0; nt < 4; nt++)
                asm volatile(
                    "mma.sync.aligned.m16n8k16.row.col.f32.bf16.bf16.f32 "
                    "{%0,%1,%2,%3}, {%4,%5,%6,%7}, {%8,%9}, {%0,%1,%2,%3};"
                    : "+f"(acc[mt][nt][0]), "+f"(acc[mt][nt][1]),
                      "+f"(acc[mt][nt][2]), "+f"(acc[mt][nt][3])
                    : "r"(a0), "r"(a1), "r"(a2), "r"(a3),
                      "r"(bf[nt][0]), "r"(bf[nt][1]));
        }
        __syncthreads();
    }

    // --- epilogue (same acc layout as m16n8k8) ---
#pragma unroll
    for (int mt = 0; mt < 4; mt++) {
#pragma unroll
        for (int half = 0; half < 2; half++) {
            const long long m = bm + wm * 64 + mt * 16 + grp + half * 8;
            float rs = 1.f;
            if (EPI == 0 && rowscale != nullptr)
                rs = basescale * __ldg(rowscale + m);
#pragma unroll
            for (int nt = 0; nt < 4; nt++) {
                const long long n = bn0 + wn * 32 + nt * 8 + 2 * tig;
                float v0 = acc[mt][nt][half * 2 + 0];
                float v1 = acc[mt][nt][half * 2 + 1];
                if (bias != nullptr) {
                    v0 += __ldg(bias + n);
                    v1 += __ldg(bias + n + 1);
                }
                if (EPI == 0) {
                    C[m * N + n]     = v0 * rs;
                    C[m * N + n + 1] = v1 * rs;
                } else {
                    const long long f = m * 512 + n;
                    C[f]     = __ldg(cur_r + f)     + 0.1f * v0;
                    C[f + 1] = __ldg(cur_r + f + 1) + 0.1f * v1;
                }
            }
        }
    }
}

// b2[n] = sum_k kW[n,k] * qb[k]   (one warp per n, fp32 exact)
__global__ __launch_bounds__(256)
void bias2_k(const float* __restrict__ kW, const float* __restrict__ qb,
             float* __restrict__ b2)
{
    const int n    = blockIdx.x * 8 + (threadIdx.x >> 5);
    const int lane = threadIdx.x & 31;
    const float* row = kW + (long long)n * 512;
    float s = 0.f;
#pragma unroll
    for (int k = lane * 4; k < 512; k += 128) {
        const float4 v = *(const float4*)(row + k);
        const float4 q = *(const float4*)(qb + k);
        s += v.x * q.x + v.y * q.y + v.z * q.z + v.w * q.w;
    }
#pragma unroll
    for (int o = 16; o; o >>= 1) s += __shfl_xor_sync(0xffffffffu, s, o);
    if (lane == 0) b2[n] = s;
}

// ---------------------------------------------------------------------------
// Two-phase attention (R13 WIN, unchanged): 81% DRAM, near roofline.
// ---------------------------------------------------------------------------
__global__ __launch_bounds__(256)
void attn_2p(const float* __restrict__ hr, const float* __restrict__ hi)
{
    __shared__ __align__(16) float shQ[DIM2];
    __shared__ float shS[SLOTS];
    __shared__ float shW[SLOTS];

    const int bt  = blockIdx.x;
    const int tid = threadIdx.x;
    const int w   = tid >> 5;
    const int c   = tid & 31;

    *(float4*)&shQ[tid * 4] = *(const float4*)(g_Qk + (size_t)bt * DIM2 + tid * 4);
    __syncthreads();

    const float* baseR = hr + (size_t)bt * (SLOTS * 512);
    const float* baseI = hi + (size_t)bt * (SLOTS * 512);

#pragma unroll
    for (int si = 0; si < 4; si++) {
        const int s = w + si * 8;
        const float* prow = baseR + (size_t)s * 512 + 4 * c;
        const float* irow = baseI + (size_t)s * 512 + 4 * c;
        float p = 0.f;
#pragma unroll
        for (int k = 0; k < 4; k++) {
            const float4 h = *(const float4*)(prow + k * 128);
            const float4 q = *(const float4*)&shQ[k * 128 + 4 * c];
            p += h.x * q.x + h.y * q.y + h.z * q.z + h.w * q.w;
        }
#pragma unroll
        for (int k = 0; k < 4; k++) {
            const float4 h = *(const float4*)(irow + k * 128);
            const float4 q = *(const float4*)&shQ[512 + k * 128 + 4 * c];
            p += h.x * q.x + h.y * q.y + h.z * q.z + h.w * q.w;
        }
#pragma unroll
        for (int off = 16; off; off >>= 1)
            p += __shfl_xor_sync(0xffffffffu, p, off);
        if (c == 0) shS[s] = p;
    }
    __syncthreads();

    if (tid < SLOTS) {
        float m = -1e30f;
#pragma unroll
        for (int i = 0; i < SLOTS; i++) m = fmaxf(m, shS[i]);
        shW[tid] = __expf(shS[tid] - m);
    }
    __syncthreads();
    float L = 0.f;
#pragma unroll
    for (int i = 0; i < SLOTS; i++) L += shW[i];
    const float invL = 1.f / L;

    const int j = tid * 4;
    const float* src = (j < 512) ? (baseR + j) : (baseI + (j - 512));
    float4 acc = make_float4(0.f, 0.f, 0.f, 0.f);
#pragma unroll 8
    for (int s = 0; s < SLOTS; s++) {
        const float4 h = *(const float4*)(src + (size_t)s * 512);
        const float ws = shW[s];
        acc.x += ws * h.x;
        acc.y += ws * h.y;
        acc.z += ws * h.z;
        acc.w += ws * h.w;
    }
    acc.x *= invL; acc.y *= invL; acc.z *= invL; acc.w *= invL;
    *(float4*)&g_wH[(size_t)bt * DIM2 + j] = acc;
}

// ---------------------------------------------------------------------------
// Host-side staged diagnostics (only on the non-captured correctness call).
// ---------------------------------------------------------------------------
static bool kl_capturing()
{
    cudaStreamCaptureStatus st = cudaStreamCaptureStatusNone;
    cudaError_t e = cudaStreamIsCapturing((cudaStream_t)0, &st);
    if (e != cudaSuccess) { (void)cudaGetLastError(); return true; }
    return st != cudaStreamCaptureStatusNone;
}
static cudaError_t kl_poll()
{
    cudaEvent_t ev;
    if (cudaEventCreateWithFlags(&ev, cudaEventDisableTiming) != cudaSuccess)
        return cudaGetLastError();
    cudaEventRecord(ev, (cudaStream_t)0);
    cudaError_t e;
    do { e = cudaEventQuery(ev); } while (e == cudaErrorNotReady);
    cudaEventDestroy(ev);
    return e;
}
static void kl_stage(bool diag, const char* name, bool* dead)
{
    if (!diag || *dead) return;
    cudaError_t e = kl_poll();
    if (e != cudaSuccess) {
        fprintf(stderr, "[KLDIAG] stage %s -> %s\n", name, cudaGetErrorString(e));
        *dead = true;
    }
}

// ---------------------------------------------------------------------------
extern "C" void kernel_launch(void* const* d_in, const int* in_sizes, int n_in,
                              void* d_out, int out_size)
{
    const bool diag = !kl_capturing();
    if (n_in < 11) return;

    // Confirmed insertion order, all fp32:
    // 0=hist_real 1=hist_imag 2=cur_r 3=cur_i 4=conf 5=qW 6=qb 7=kW 8=kb 9=vW 10=vb
    const float* hr   = (const float*)d_in[0];
    const float* hi   = (const float*)d_in[1];
    const float* cr   = (const float*)d_in[2];
    const float* ci   = (const float*)d_in[3];
    const float* conf = (const float*)d_in[4];
    const float* qW   = (const float*)d_in[5];
    const float* qb   = (const float*)d_in[6];
    const float* kW   = (const float*)d_in[7];
    // d_in[8] = kb: softmax-invariant, unused
    const float* vW   = (const float*)d_in[9];
    const float* vb   = (const float*)d_in[10];
    float* out = (float*)d_out;   // out_size fp32 elements = real part

    float *pW2 = nullptr, *pB2 = nullptr, *pQk = nullptr, *pwH = nullptr;
    cudaGetSymbolAddress((void**)&pW2, g_W2);
    cudaGetSymbolAddress((void**)&pB2, g_b2);
    cudaGetSymbolAddress((void**)&pQk, g_Qk);
    cudaGetSymbolAddress((void**)&pwH, g_wH);
    if (!pW2 || !pB2 || !pQk || !pwH) return;

    const float scale = 0.044194173824159216f;   // 512^-0.5
    bool dead = false;

    // 1a) W2 = qW @ kW^T   [1024,1024], K=512
    gemm_bf<0, 1, 0><<<dim3(DIM2 / 128, DIM2 / 128), 256>>>(
        qW, nullptr, kW, 0, nullptr, nullptr, 1.f, nullptr, pW2,
        DIM2, DIM2, DIM);
    // 1b) b2 = kW @ qb
    bias2_k<<<DIM2 / 8, 256>>>(kW, qb, pB2);
    kl_stage(diag, "w2", &dead);
    if (dead) return;

    // 2) Qk = (cur2 @ W2 + b2) * scale * conf[m]   [4096,1024], K=1024
    gemm_bf<1, 0, 0><<<dim3(DIM2 / 128, BT / 128), 256>>>(
        cr, ci, pW2, DIM2, pB2, conf, scale, nullptr, pQk, BT, DIM2, DIM2);
    kl_stage(diag, "qk", &dead);
    if (dead) return;

    // 3) two-phase softmax attention -> g_wH
    attn_2p<<<BT, 256>>>(hr, hi);
    kl_stage(diag, "attn", &dead);
    if (dead) return;

    // 4) out = cur_r + 0.1 * (wH @ vW[:,0:512] + vb[0:512])   (real part)
    gemm_bf<0, 0, 1><<<dim3(DIM / 128, BT / 128), 256>>>(
        pwH, nullptr, vW, DIM2, vb, nullptr, 1.f, cr, out, BT, DIM, DIM2);
    kl_stage(diag, "gemm4", &dead);
}